// round 1
// baseline (speedup 1.0000x reference)
#include <cuda_runtime.h>

#define Bb 4
#define Ss 2048
#define Dd 1024
#define Hh 16
#define HDi 64
#define HALFd 32
#define NTOK (Bb*Ss)

// Scratch (device globals; no dynamic allocation allowed)
__device__ float g_q[NTOK*Dd];   // [B,H,S,HD]
__device__ float g_k[NTOK*Dd];   // [B,H,S,HD]
__device__ float g_v[NTOK*Dd];   // [B,H,S,HD]
__device__ float g_ao[NTOK*Dd];  // [B,S,D] attention output

// ---------------------------------------------------------------------------
// 128x128x8 SGEMM: Y = A @ W^T
// MODE 0: A = x, W selected by blockIdx.z (wq/wk/wv); epilogue applies RoPE
//         (z<2) and scatters to [B,H,S,HD] scratch.
// MODE 1: A = g_ao, W = wo; plain epilogue to row-major out.
// ---------------------------------------------------------------------------
template<int MODE>
__global__ void __launch_bounds__(256) gemm128(
    const float* __restrict__ A,
    const float* __restrict__ W0,
    const float* __restrict__ W1,
    const float* __restrict__ W2,
    const float* __restrict__ cosf,
    const float* __restrict__ sinf,
    float* __restrict__ outp)
{
    __shared__ float As[8][128];
    __shared__ float Bs[8][128];

    const int z = (MODE == 0) ? blockIdx.z : 0;
    const float* W  = (MODE == 0) ? (z == 0 ? W0 : (z == 1 ? W1 : W2)) : W0;
    const float* Ap = (MODE == 0) ? A : g_ao;

    const int tid = threadIdx.x;
    const int tx = tid & 15, ty = tid >> 4;
    const int m0 = blockIdx.y * 128, n0 = blockIdx.x * 128;

    const int lrow = tid >> 1;
    const int lk   = (tid & 1) * 4;
    const float* Ag = Ap + (size_t)(m0 + lrow) * Dd + lk;
    const float* Wg = W  + (size_t)(n0 + lrow) * Dd + lk;

    float acc[8][8];
    #pragma unroll
    for (int i = 0; i < 8; i++)
        #pragma unroll
        for (int j = 0; j < 8; j++) acc[i][j] = 0.f;

    for (int k0 = 0; k0 < Dd; k0 += 8) {
        float4 av = *(const float4*)(Ag + k0);
        float4 wv = *(const float4*)(Wg + k0);
        __syncthreads();
        As[lk+0][lrow] = av.x; As[lk+1][lrow] = av.y;
        As[lk+2][lrow] = av.z; As[lk+3][lrow] = av.w;
        Bs[lk+0][lrow] = wv.x; Bs[lk+1][lrow] = wv.y;
        Bs[lk+2][lrow] = wv.z; Bs[lk+3][lrow] = wv.w;
        __syncthreads();
        #pragma unroll
        for (int kk = 0; kk < 8; kk++) {
            float a[8], b[8];
            *(float4*)&a[0] = *(const float4*)&As[kk][ty*8];
            *(float4*)&a[4] = *(const float4*)&As[kk][ty*8+4];
            *(float4*)&b[0] = *(const float4*)&Bs[kk][tx*8];
            *(float4*)&b[4] = *(const float4*)&Bs[kk][tx*8+4];
            #pragma unroll
            for (int i = 0; i < 8; i++)
                #pragma unroll
                for (int j = 0; j < 8; j++)
                    acc[i][j] += a[i] * b[j];
        }
    }

    if (MODE == 0) {
        float* dst = (z == 0) ? g_q : (z == 1 ? g_k : g_v);
        #pragma unroll
        for (int i = 0; i < 8; i++) {
            int m  = m0 + ty*8 + i;
            int bb = m / Ss;
            int sp = m % Ss;
            #pragma unroll
            for (int j = 0; j < 8; j += 2) {
                int n    = n0 + tx*8 + j;
                int head = n >> 6;
                int hd   = n & 63;
                float v0 = acc[i][j], v1 = acc[i][j+1];
                if (z < 2) {
                    float c  = cosf[sp*HALFd + (hd >> 1)];
                    float sn = sinf[sp*HALFd + (hd >> 1)];
                    float o0 = v0*c - v1*sn;
                    float o1 = v0*sn + v1*c;
                    v0 = o0; v1 = o1;
                }
                int idx = (((bb*Hh + head)*Ss) + sp)*HDi + hd;
                *(float2*)&dst[idx] = make_float2(v0, v1);
            }
        }
    } else {
        #pragma unroll
        for (int i = 0; i < 8; i++) {
            int m = m0 + ty*8 + i;
            *(float4*)&outp[(size_t)m*Dd + n0 + tx*8]     = *(float4*)&acc[i][0];
            *(float4*)&outp[(size_t)m*Dd + n0 + tx*8 + 4] = *(float4*)&acc[i][4];
        }
    }
}

// ---------------------------------------------------------------------------
// Flash attention: causal, online softmax.
// Block: 64 queries x full HD=64. Key tiles of 64. 256 threads, 4x4 microtiles.
// Smem: Qs[64][64], Ks[64][65] (reused as P), Vs[64][64]  = 49,408 B dynamic.
// ---------------------------------------------------------------------------
#define LDK 65
#define ATTN_SMEM ((64*64 + 64*LDK + 64*64) * 4)

__global__ void __launch_bounds__(256) attn_kernel()
{
    extern __shared__ float sm[];
    float* Qs = sm;                 // [64][64]
    float* Ks = sm + 64*64;         // [64][65]
    float* Vs = Ks + 64*LDK;        // [64][64]
    float* Ps = Ks;                 // reuse

    const int bh = blockIdx.y;          // 0..63  (b*H + h)
    const int qt = blockIdx.x;          // 0..31
    const int q0 = qt * 64;
    const float* qb = g_q + (size_t)bh * Ss * HDi;
    const float* kb = g_k + (size_t)bh * Ss * HDi;
    const float* vb = g_v + (size_t)bh * Ss * HDi;

    const int tid = threadIdx.x;
    const int tx = tid & 15, ty = tid >> 4;

    // Load Q tile (float4, row-major [row][d])
    #pragma unroll
    for (int t = 0; t < 4; t++) {
        int s = tid + t*256;
        int row = s >> 4, d4 = (s & 15) * 4;
        *(float4*)&Qs[row*64 + d4] = *(const float4*)&qb[(q0+row)*HDi + d4];
    }

    float m_i[4], l_i[4], o[4][4];
    #pragma unroll
    for (int i = 0; i < 4; i++) {
        m_i[i] = -1e30f; l_i[i] = 0.f;
        #pragma unroll
        for (int j = 0; j < 4; j++) o[i][j] = 0.f;
    }

    for (int kt = 0; kt <= qt; kt++) {
        const int k0 = kt * 64;
        __syncthreads();   // protect Ks(=Ps)/Vs from previous iteration readers
        #pragma unroll
        for (int t = 0; t < 4; t++) {
            int s = tid + t*256;
            int row = s >> 4, d4 = (s & 15) * 4;
            float4 kv = *(const float4*)&kb[(k0+row)*HDi + d4];
            Ks[row*LDK + d4 + 0] = kv.x;
            Ks[row*LDK + d4 + 1] = kv.y;
            Ks[row*LDK + d4 + 2] = kv.z;
            Ks[row*LDK + d4 + 3] = kv.w;
            *(float4*)&Vs[row*64 + d4] = *(const float4*)&vb[(k0+row)*HDi + d4];
        }
        __syncthreads();

        // Scores: 4 rows (ty*4+i) x 4 keys (tx + 16*j)
        float sc[4][4];
        #pragma unroll
        for (int i = 0; i < 4; i++)
            #pragma unroll
            for (int j = 0; j < 4; j++) sc[i][j] = 0.f;

        #pragma unroll 4
        for (int d = 0; d < 64; d++) {
            float qv[4], kv[4];
            #pragma unroll
            for (int i = 0; i < 4; i++) qv[i] = Qs[(ty*4 + i)*64 + d];
            #pragma unroll
            for (int j = 0; j < 4; j++) kv[j] = Ks[(tx + 16*j)*LDK + d];
            #pragma unroll
            for (int i = 0; i < 4; i++)
                #pragma unroll
                for (int j = 0; j < 4; j++)
                    sc[i][j] += qv[i] * kv[j];
        }

        // Scale + causal mask
        #pragma unroll
        for (int i = 0; i < 4; i++) {
            int qg = q0 + ty*4 + i;
            #pragma unroll
            for (int j = 0; j < 4; j++) {
                int kg = k0 + tx + 16*j;
                sc[i][j] = (kg <= qg) ? sc[i][j] * 0.125f : -1e30f;
            }
        }

        // Online softmax update (row-wise, reduce across tx via shfl width 16)
        #pragma unroll
        for (int i = 0; i < 4; i++) {
            float rm = fmaxf(fmaxf(sc[i][0], sc[i][1]), fmaxf(sc[i][2], sc[i][3]));
            #pragma unroll
            for (int off = 8; off >= 1; off >>= 1)
                rm = fmaxf(rm, __shfl_xor_sync(0xffffffffu, rm, off));
            float mn = fmaxf(m_i[i], rm);
            float al = __expf(m_i[i] - mn);
            float rs = 0.f;
            #pragma unroll
            for (int j = 0; j < 4; j++) {
                sc[i][j] = __expf(sc[i][j] - mn);
                rs += sc[i][j];
            }
            #pragma unroll
            for (int off = 8; off >= 1; off >>= 1)
                rs += __shfl_xor_sync(0xffffffffu, rs, off);
            l_i[i] = l_i[i] * al + rs;
            m_i[i] = mn;
            #pragma unroll
            for (int j = 0; j < 4; j++) o[i][j] *= al;
        }

        __syncthreads();   // all reads of Ks done before overwrite as Ps
        #pragma unroll
        for (int i = 0; i < 4; i++)
            #pragma unroll
            for (int j = 0; j < 4; j++)
                Ps[(ty*4 + i)*LDK + tx + 16*j] = sc[i][j];
        __syncthreads();

        // O += P @ V  (4 rows x 4 dims = tx*4..tx*4+3)
        #pragma unroll 4
        for (int kk = 0; kk < 64; kk++) {
            float p[4];
            #pragma unroll
            for (int i = 0; i < 4; i++) p[i] = Ps[(ty*4 + i)*LDK + kk];
            float4 vv = *(float4*)&Vs[kk*64 + tx*4];
            #pragma unroll
            for (int i = 0; i < 4; i++) {
                o[i][0] += p[i] * vv.x;
                o[i][1] += p[i] * vv.y;
                o[i][2] += p[i] * vv.z;
                o[i][3] += p[i] * vv.w;
            }
        }
    }

    // Epilogue: write [B,S,D] layout (b, q, h*64 + dim)
    const int b_ = bh >> 4;
    const int h_ = bh & 15;
    #pragma unroll
    for (int i = 0; i < 4; i++) {
        int qg = q0 + ty*4 + i;
        float inv = 1.f / l_i[i];
        float4 o4 = make_float4(o[i][0]*inv, o[i][1]*inv, o[i][2]*inv, o[i][3]*inv);
        *(float4*)&g_ao[((size_t)(b_*Ss + qg))*Dd + h_*HDi + tx*4] = o4;
    }
}

// ---------------------------------------------------------------------------
extern "C" void kernel_launch(void* const* d_in, const int* in_sizes, int n_in,
                              void* d_out, int out_size)
{
    const float* x  = (const float*)d_in[0];
    const float* fc = (const float*)d_in[1];
    const float* fs = (const float*)d_in[2];
    const float* wq = (const float*)d_in[3];
    const float* wk = (const float*)d_in[4];
    const float* wv = (const float*)d_in[5];
    const float* wo = (const float*)d_in[6];
    float* out = (float*)d_out;

    // Idempotent; ignore status (first uncaptured call sets it persistently).
    cudaFuncSetAttribute(attn_kernel,
                         cudaFuncAttributeMaxDynamicSharedMemorySize, ATTN_SMEM);

    // QKV projections + RoPE + transpose
    gemm128<0><<<dim3(Dd/128, NTOK/128, 3), 256>>>(x, wq, wk, wv, fc, fs, nullptr);

    // Causal flash attention
    attn_kernel<<<dim3(Ss/64, Bb*Hh), 256, ATTN_SMEM>>>();

    // Output projection
    gemm128<1><<<dim3(Dd/128, NTOK/128, 1), 256>>>(nullptr, wo, nullptr, nullptr,
                                                   nullptr, nullptr, out);
}

// round 6
// speedup vs baseline: 1.5990x; 1.5990x over previous
#include <cuda_runtime.h>
#include <cstdint>

#define Bb 4
#define Ss 2048
#define Dd 1024
#define Hh 16
#define HDi 64
#define NTOK (Bb*Ss)

// Scratch (device globals; no dynamic allocation allowed)
__device__ float g_q[NTOK*Dd];   // [B,H,S,HD]
__device__ float g_k[NTOK*Dd];   // [B,H,S,HD]
__device__ float g_v[NTOK*Dd];   // [B,H,S,HD]
__device__ float g_ao[NTOK*Dd];  // [B,S,D] attention output

__device__ __forceinline__ uint32_t f2tf(float f) {
    uint32_t r;
    asm("cvt.rna.tf32.f32 %0, %1;" : "=r"(r) : "f"(f));
    return r;
}
__device__ __forceinline__ void mma_tf32(float* d, uint32_t a0, uint32_t a1,
                                         uint32_t a2, uint32_t a3,
                                         uint32_t b0, uint32_t b1) {
    asm volatile(
        "mma.sync.aligned.m16n8k8.row.col.f32.tf32.tf32.f32 "
        "{%0,%1,%2,%3}, {%4,%5,%6,%7}, {%8,%9}, {%0,%1,%2,%3};"
        : "+f"(d[0]), "+f"(d[1]), "+f"(d[2]), "+f"(d[3])
        : "r"(a0), "r"(a1), "r"(a2), "r"(a3), "r"(b0), "r"(b1));
}

// ---------------------------------------------------------------------------
// tf32 mma.sync GEMM: Y = A @ W^T  (M=8192, N=1024, K=1024)
// CTA 128x128, K-chunk 32, 8 warps (4x2), warp tile 32x64.
// SMEM: stride 40 words/row; k8 groups permuted [0,4,1,5,2,6,3,7] with
// XOR 2*(row&3) swizzle -> conflict-free STS.32 stores and LDS.64 frag loads.
// MODE 0: A=x, W per blockIdx.z (wq/wk/wv); epilogue RoPE (z<2) + scatter to
//         [B,H,S,HD]. MODE 1: A=g_ao, W=wo; row-major out.
// ---------------------------------------------------------------------------
#define SRow 40
#define BUFW (128*SRow)            // words per matrix tile
#define GSM  (2*2*BUFW*4)          // 2 bufs x (A+B) = 81920 B

template<int MODE>
__global__ void __launch_bounds__(256) gemm_mma(
    const float* __restrict__ A,
    const float* __restrict__ W0,
    const float* __restrict__ W1,
    const float* __restrict__ W2,
    const float* __restrict__ fcos,
    const float* __restrict__ fsin,
    float* __restrict__ outp)
{
    extern __shared__ uint32_t su[];

    const int tid  = threadIdx.x;
    const int wid  = tid >> 5, lane = tid & 31;
    const int grp  = lane >> 2, tig = lane & 3;
    const int wm   = (wid >> 1) * 32;       // warp M offset
    const int wn   = (wid & 1) * 64;        // warp N offset
    const int z    = (MODE == 0) ? blockIdx.z : 0;
    const float* W  = (MODE == 0) ? (z == 0 ? W0 : (z == 1 ? W1 : W2)) : W0;
    const float* Ap = (MODE == 0) ? A : g_ao;
    const int m0 = blockIdx.y * 128, n0 = blockIdx.x * 128;

    // Loader mapping: row lr+32t, 16B group lc
    const int lr = tid >> 3, lc = tid & 7;
    const float* aP = Ap + (size_t)(m0 + lr) * Dd + lc * 4;
    const float* wP = W  + (size_t)(n0 + lr) * Dd + lc * 4;

    float4 ra[4], rb[4];
    auto LOADK = [&](int k0) {
        #pragma unroll
        for (int t = 0; t < 4; t++) {
            ra[t] = *(const float4*)(aP + (size_t)(32*t) * Dd + k0);
            rb[t] = *(const float4*)(wP + (size_t)(32*t) * Dd + k0);
        }
    };
    auto STOREK = [&](int s) {
        const int base = s * 2 * BUFW;
        #pragma unroll
        for (int t = 0; t < 4; t++) {
            const int r  = lr + 32*t;
            const int rx = (r & 3) * 2;
            const int wA = base + r*SRow + (lc >> 1) * 8;
            const int wB = wA + BUFW;
            const float* fa = (const float*)&ra[t];
            const float* fb = (const float*)&rb[t];
            #pragma unroll
            for (int j = 0; j < 4; j++) {
                const int q = ((2*j + (lc & 1)) ^ rx);
                su[wA + q] = f2tf(fa[j]);
                su[wB + q] = f2tf(fb[j]);
            }
        }
    };

    float acc[2][8][4];
    #pragma unroll
    for (int i = 0; i < 2; i++)
        #pragma unroll
        for (int t = 0; t < 8; t++)
            #pragma unroll
            for (int c = 0; c < 4; c++) acc[i][t][c] = 0.f;

    const int axor = (grp & 3) * 2;
    const int aoff = (2*tig) ^ axor;

    LOADK(0);
    STOREK(0);
    __syncthreads();

    const int NCH = Dd / 32;
    for (int i = 0; i < NCH; i++) {
        const int s = i & 1;
        if (i + 1 < NCH) LOADK((i + 1) * 32);
        const int Ab = s * 2 * BUFW;
        const int Bbw = Ab + BUFW;
        #pragma unroll
        for (int g = 0; g < 4; g++) {
            uint2 af[2][2];
            #pragma unroll
            for (int mi = 0; mi < 2; mi++) {
                const int r  = wm + 16*mi + grp;
                const int w0 = Ab + r*SRow + g*8 + aoff;
                af[mi][0] = *(const uint2*)&su[w0];
                af[mi][1] = *(const uint2*)&su[w0 + 8*SRow];
            }
            #pragma unroll
            for (int t = 0; t < 8; t++) {
                const int rn = wn + 8*t + grp;
                const uint2 bf = *(const uint2*)&su[Bbw + rn*SRow + g*8 + aoff];
                #pragma unroll
                for (int mi = 0; mi < 2; mi++)
                    mma_tf32(acc[mi][t],
                             af[mi][0].x, af[mi][1].x, af[mi][0].y, af[mi][1].y,
                             bf.x, bf.y);
            }
        }
        if (i + 1 < NCH) STOREK(s ^ 1);
        __syncthreads();
    }

    // Epilogue: thread owns rows (wm+16i+grp, +8), cols (wn+8t+2*tig, +1)
    #pragma unroll
    for (int mi = 0; mi < 2; mi++) {
        #pragma unroll
        for (int h = 0; h < 2; h++) {
            const int m  = m0 + wm + 16*mi + grp + 8*h;
            if (MODE == 0) {
                const int bb = m >> 11, sp = m & 2047;
                const float* cR = fcos + sp * 32;
                const float* sR = fsin + sp * 32;
                float* dstB = (z == 0 ? g_q : (z == 1 ? g_k : g_v));
                #pragma unroll
                for (int t = 0; t < 8; t++) {
                    const int n    = n0 + wn + 8*t + 2*tig;
                    const int head = n >> 6, hd = n & 63;
                    float v0 = acc[mi][t][2*h], v1 = acc[mi][t][2*h + 1];
                    if (z < 2) {
                        const float c  = cR[hd >> 1];
                        const float sn = sR[hd >> 1];
                        const float o0 = v0*c - v1*sn;
                        const float o1 = v0*sn + v1*c;
                        v0 = o0; v1 = o1;
                    }
                    const size_t idx =
                        ((size_t)((bb * Hh + head) * Ss + sp)) * HDi + hd;
                    *(float2*)&dstB[idx] = make_float2(v0, v1);
                }
            } else {
                #pragma unroll
                for (int t = 0; t < 8; t++) {
                    const int n = n0 + wn + 8*t + 2*tig;
                    *(float2*)&outp[(size_t)m * Dd + n] =
                        make_float2(acc[mi][t][2*h], acc[mi][t][2*h + 1]);
                }
            }
        }
    }
}

// ---------------------------------------------------------------------------
// Flash attention: causal, online softmax (unchanged from R1 — passed).
// ---------------------------------------------------------------------------
#define LDK 65
#define ATTN_SMEM ((64*64 + 64*LDK + 64*64) * 4)

__global__ void __launch_bounds__(256) attn_kernel()
{
    extern __shared__ float sm[];
    float* Qs = sm;                 // [64][64]
    float* Ks = sm + 64*64;         // [64][65]
    float* Vs = Ks + 64*LDK;        // [64][64]
    float* Ps = Ks;                 // reuse

    const int bh = blockIdx.y;
    const int qt = blockIdx.x;
    const int q0 = qt * 64;
    const float* qb = g_q + (size_t)bh * Ss * HDi;
    const float* kb = g_k + (size_t)bh * Ss * HDi;
    const float* vb = g_v + (size_t)bh * Ss * HDi;

    const int tid = threadIdx.x;
    const int tx = tid & 15, ty = tid >> 4;

    #pragma unroll
    for (int t = 0; t < 4; t++) {
        int s = tid + t*256;
        int row = s >> 4, d4 = (s & 15) * 4;
        *(float4*)&Qs[row*64 + d4] = *(const float4*)&qb[(q0+row)*HDi + d4];
    }

    float m_i[4], l_i[4], o[4][4];
    #pragma unroll
    for (int i = 0; i < 4; i++) {
        m_i[i] = -1e30f; l_i[i] = 0.f;
        #pragma unroll
        for (int j = 0; j < 4; j++) o[i][j] = 0.f;
    }

    for (int kt = 0; kt <= qt; kt++) {
        const int k0 = kt * 64;
        __syncthreads();
        #pragma unroll
        for (int t = 0; t < 4; t++) {
            int s = tid + t*256;
            int row = s >> 4, d4 = (s & 15) * 4;
            float4 kv = *(const float4*)&kb[(k0+row)*HDi + d4];
            Ks[row*LDK + d4 + 0] = kv.x;
            Ks[row*LDK + d4 + 1] = kv.y;
            Ks[row*LDK + d4 + 2] = kv.z;
            Ks[row*LDK + d4 + 3] = kv.w;
            *(float4*)&Vs[row*64 + d4] = *(const float4*)&vb[(k0+row)*HDi + d4];
        }
        __syncthreads();

        float sc[4][4];
        #pragma unroll
        for (int i = 0; i < 4; i++)
            #pragma unroll
            for (int j = 0; j < 4; j++) sc[i][j] = 0.f;

        #pragma unroll 4
        for (int d = 0; d < 64; d++) {
            float qv[4], kv[4];
            #pragma unroll
            for (int i = 0; i < 4; i++) qv[i] = Qs[(ty*4 + i)*64 + d];
            #pragma unroll
            for (int j = 0; j < 4; j++) kv[j] = Ks[(tx + 16*j)*LDK + d];
            #pragma unroll
            for (int i = 0; i < 4; i++)
                #pragma unroll
                for (int j = 0; j < 4; j++)
                    sc[i][j] += qv[i] * kv[j];
        }

        #pragma unroll
        for (int i = 0; i < 4; i++) {
            int qg = q0 + ty*4 + i;
            #pragma unroll
            for (int j = 0; j < 4; j++) {
                int kg = k0 + tx + 16*j;
                sc[i][j] = (kg <= qg) ? sc[i][j] * 0.125f : -1e30f;
            }
        }

        #pragma unroll
        for (int i = 0; i < 4; i++) {
            float rm = fmaxf(fmaxf(sc[i][0], sc[i][1]), fmaxf(sc[i][2], sc[i][3]));
            #pragma unroll
            for (int off = 8; off >= 1; off >>= 1)
                rm = fmaxf(rm, __shfl_xor_sync(0xffffffffu, rm, off));
            float mn = fmaxf(m_i[i], rm);
            float al = __expf(m_i[i] - mn);
            float rs = 0.f;
            #pragma unroll
            for (int j = 0; j < 4; j++) {
                sc[i][j] = __expf(sc[i][j] - mn);
                rs += sc[i][j];
            }
            #pragma unroll
            for (int off = 8; off >= 1; off >>= 1)
                rs += __shfl_xor_sync(0xffffffffu, rs, off);
            l_i[i] = l_i[i] * al + rs;
            m_i[i] = mn;
            #pragma unroll
            for (int j = 0; j < 4; j++) o[i][j] *= al;
        }

        __syncthreads();
        #pragma unroll
        for (int i = 0; i < 4; i++)
            #pragma unroll
            for (int j = 0; j < 4; j++)
                Ps[(ty*4 + i)*LDK + tx + 16*j] = sc[i][j];
        __syncthreads();

        #pragma unroll 4
        for (int kk = 0; kk < 64; kk++) {
            float p[4];
            #pragma unroll
            for (int i = 0; i < 4; i++) p[i] = Ps[(ty*4 + i)*LDK + kk];
            float4 vv = *(float4*)&Vs[kk*64 + tx*4];
            #pragma unroll
            for (int i = 0; i < 4; i++) {
                o[i][0] += p[i] * vv.x;
                o[i][1] += p[i] * vv.y;
                o[i][2] += p[i] * vv.z;
                o[i][3] += p[i] * vv.w;
            }
        }
    }

    const int b_ = bh >> 4;
    const int h_ = bh & 15;
    #pragma unroll
    for (int i = 0; i < 4; i++) {
        int qg = q0 + ty*4 + i;
        float inv = 1.f / l_i[i];
        float4 o4 = make_float4(o[i][0]*inv, o[i][1]*inv, o[i][2]*inv, o[i][3]*inv);
        *(float4*)&g_ao[((size_t)(b_*Ss + qg))*Dd + h_*HDi + tx*4] = o4;
    }
}

// ---------------------------------------------------------------------------
extern "C" void kernel_launch(void* const* d_in, const int* in_sizes, int n_in,
                              void* d_out, int out_size)
{
    const float* x  = (const float*)d_in[0];
    const float* fc = (const float*)d_in[1];
    const float* fs = (const float*)d_in[2];
    const float* wq = (const float*)d_in[3];
    const float* wk = (const float*)d_in[4];
    const float* wv = (const float*)d_in[5];
    const float* wo = (const float*)d_in[6];
    float* out = (float*)d_out;

    cudaFuncSetAttribute(gemm_mma<0>, cudaFuncAttributeMaxDynamicSharedMemorySize, GSM);
    cudaFuncSetAttribute(gemm_mma<1>, cudaFuncAttributeMaxDynamicSharedMemorySize, GSM);
    cudaFuncSetAttribute(attn_kernel, cudaFuncAttributeMaxDynamicSharedMemorySize, ATTN_SMEM);

    // QKV projections (tf32 mma.sync) + RoPE + transpose
    gemm_mma<0><<<dim3(Dd/128, NTOK/128, 3), 256, GSM>>>(x, wq, wk, wv, fc, fs, nullptr);

    // Causal flash attention (fp32 SIMT)
    attn_kernel<<<dim3(Ss/64, Bb*Hh), 256, ATTN_SMEM>>>();

    // Output projection (tf32 mma.sync)
    gemm_mma<1><<<dim3(Dd/128, NTOK/128, 1), 256, GSM>>>(nullptr, wo, nullptr, nullptr,
                                                         nullptr, nullptr, out);
}

// round 9
// speedup vs baseline: 2.6406x; 1.6514x over previous
#include <cuda_runtime.h>
#include <cstdint>

#define Bb 4
#define Ss 2048
#define Dd 1024
#define Hh 16
#define HDi 64
#define NTOK (Bb*Ss)

// Scratch (device globals; no dynamic allocation allowed)
__device__ float g_q[NTOK*Dd];   // [B,H,S,HD]
__device__ float g_k[NTOK*Dd];   // [B,H,S,HD]
__device__ float g_v[NTOK*Dd];   // [B,H,S,HD]
__device__ float g_ao[NTOK*Dd];  // [B,S,D] attention output

__device__ __forceinline__ uint32_t f2tf(float f) {
    uint32_t r;
    asm("cvt.rna.tf32.f32 %0, %1;" : "=r"(r) : "f"(f));
    return r;
}
__device__ __forceinline__ void mma_tf32(float* d, uint32_t a0, uint32_t a1,
                                         uint32_t a2, uint32_t a3,
                                         uint32_t b0, uint32_t b1) {
    asm volatile(
        "mma.sync.aligned.m16n8k8.row.col.f32.tf32.tf32.f32 "
        "{%0,%1,%2,%3}, {%4,%5,%6,%7}, {%8,%9}, {%0,%1,%2,%3};"
        : "+f"(d[0]), "+f"(d[1]), "+f"(d[2]), "+f"(d[3])
        : "r"(a0), "r"(a1), "r"(a2), "r"(a3), "r"(b0), "r"(b1));
}

// ---------------------------------------------------------------------------
// tf32 mma.sync GEMM: Y = A @ W^T  (unchanged from R6 — passed)
// ---------------------------------------------------------------------------
#define SRow 40
#define BUFW (128*SRow)
#define GSM  (2*2*BUFW*4)

template<int MODE>
__global__ void __launch_bounds__(256) gemm_mma(
    const float* __restrict__ A,
    const float* __restrict__ W0,
    const float* __restrict__ W1,
    const float* __restrict__ W2,
    const float* __restrict__ fcos,
    const float* __restrict__ fsin,
    float* __restrict__ outp)
{
    extern __shared__ uint32_t su[];

    const int tid  = threadIdx.x;
    const int wid  = tid >> 5, lane = tid & 31;
    const int grp  = lane >> 2, tig = lane & 3;
    const int wm   = (wid >> 1) * 32;
    const int wn   = (wid & 1) * 64;
    const int z    = (MODE == 0) ? blockIdx.z : 0;
    const float* W  = (MODE == 0) ? (z == 0 ? W0 : (z == 1 ? W1 : W2)) : W0;
    const float* Ap = (MODE == 0) ? A : g_ao;
    const int m0 = blockIdx.y * 128, n0 = blockIdx.x * 128;

    const int lr = tid >> 3, lc = tid & 7;
    const float* aP = Ap + (size_t)(m0 + lr) * Dd + lc * 4;
    const float* wP = W  + (size_t)(n0 + lr) * Dd + lc * 4;

    float4 ra[4], rb[4];
    auto LOADK = [&](int k0) {
        #pragma unroll
        for (int t = 0; t < 4; t++) {
            ra[t] = *(const float4*)(aP + (size_t)(32*t) * Dd + k0);
            rb[t] = *(const float4*)(wP + (size_t)(32*t) * Dd + k0);
        }
    };
    auto STOREK = [&](int s) {
        const int base = s * 2 * BUFW;
        #pragma unroll
        for (int t = 0; t < 4; t++) {
            const int r  = lr + 32*t;
            const int rx = (r & 3) * 2;
            const int wA = base + r*SRow + (lc >> 1) * 8;
            const int wB = wA + BUFW;
            const float* fa = (const float*)&ra[t];
            const float* fb = (const float*)&rb[t];
            #pragma unroll
            for (int j = 0; j < 4; j++) {
                const int q = ((2*j + (lc & 1)) ^ rx);
                su[wA + q] = f2tf(fa[j]);
                su[wB + q] = f2tf(fb[j]);
            }
        }
    };

    float acc[2][8][4];
    #pragma unroll
    for (int i = 0; i < 2; i++)
        #pragma unroll
        for (int t = 0; t < 8; t++)
            #pragma unroll
            for (int c = 0; c < 4; c++) acc[i][t][c] = 0.f;

    const int axor = (grp & 3) * 2;
    const int aoff = (2*tig) ^ axor;

    LOADK(0);
    STOREK(0);
    __syncthreads();

    const int NCH = Dd / 32;
    for (int i = 0; i < NCH; i++) {
        const int s = i & 1;
        if (i + 1 < NCH) LOADK((i + 1) * 32);
        const int Ab = s * 2 * BUFW;
        const int Bbw = Ab + BUFW;
        #pragma unroll
        for (int g = 0; g < 4; g++) {
            uint2 af[2][2];
            #pragma unroll
            for (int mi = 0; mi < 2; mi++) {
                const int r  = wm + 16*mi + grp;
                const int w0 = Ab + r*SRow + g*8 + aoff;
                af[mi][0] = *(const uint2*)&su[w0];
                af[mi][1] = *(const uint2*)&su[w0 + 8*SRow];
            }
            #pragma unroll
            for (int t = 0; t < 8; t++) {
                const int rn = wn + 8*t + grp;
                const uint2 bf = *(const uint2*)&su[Bbw + rn*SRow + g*8 + aoff];
                #pragma unroll
                for (int mi = 0; mi < 2; mi++)
                    mma_tf32(acc[mi][t],
                             af[mi][0].x, af[mi][1].x, af[mi][0].y, af[mi][1].y,
                             bf.x, bf.y);
            }
        }
        if (i + 1 < NCH) STOREK(s ^ 1);
        __syncthreads();
    }

    #pragma unroll
    for (int mi = 0; mi < 2; mi++) {
        #pragma unroll
        for (int h = 0; h < 2; h++) {
            const int m  = m0 + wm + 16*mi + grp + 8*h;
            if (MODE == 0) {
                const int bb = m >> 11, sp = m & 2047;
                const float* cR = fcos + sp * 32;
                const float* sR = fsin + sp * 32;
                float* dstB = (z == 0 ? g_q : (z == 1 ? g_k : g_v));
                #pragma unroll
                for (int t = 0; t < 8; t++) {
                    const int n    = n0 + wn + 8*t + 2*tig;
                    const int head = n >> 6, hd = n & 63;
                    float v0 = acc[mi][t][2*h], v1 = acc[mi][t][2*h + 1];
                    if (z < 2) {
                        const float c  = cR[hd >> 1];
                        const float sn = sR[hd >> 1];
                        const float o0 = v0*c - v1*sn;
                        const float o1 = v0*sn + v1*c;
                        v0 = o0; v1 = o1;
                    }
                    const size_t idx =
                        ((size_t)((bb * Hh + head) * Ss + sp)) * HDi + hd;
                    *(float2*)&dstB[idx] = make_float2(v0, v1);
                }
            } else {
                #pragma unroll
                for (int t = 0; t < 8; t++) {
                    const int n = n0 + wn + 8*t + 2*tig;
                    *(float2*)&outp[(size_t)m * Dd + n] =
                        make_float2(acc[mi][t][2*h], acc[mi][t][2*h + 1]);
                }
            }
        }
    }
}

// ---------------------------------------------------------------------------
// Flash attention with tf32 mma.sync.
// Block: 128 q-rows, key tiles of 64. 8 warps; warp = 16 q-rows x 64 keys.
// Smem (words, RS=72/row): QP[128] (Q stage -> per-warp P), Ks[64], Vts[64].
// ---------------------------------------------------------------------------
#define RS 72
#define QP_OFF 0
#define KS_OFF (128*RS)
#define VT_OFF (KS_OFF + 64*RS)
#define ASMEM ((VT_OFF + 64*RS)*4)   // 73728 B

__device__ __forceinline__ void st_perm(uint32_t* s, int row, int fc,
                                        float4 v, float scale) {
    const int base = row*RS + (fc >> 1)*8;
    const int rx = (row & 3)*2;
    const float* f = (const float*)&v;
    #pragma unroll
    for (int j = 0; j < 4; j++) {
        const int q = (2*j + (fc & 1)) ^ rx;
        s[base + q] = f2tf(f[j]*scale);
    }
}

__global__ void __launch_bounds__(256) attn_mma()
{
    extern __shared__ uint32_t su[];
    const int tid = threadIdx.x, wid = tid >> 5, lane = tid & 31;
    const int grp = lane >> 2, tig = lane & 3;
    const int bh = blockIdx.y;
    const int qt = gridDim.x - 1 - blockIdx.x;   // long blocks first
    const int q0 = qt * 128;
    const float* qb = g_q + (size_t)bh * Ss * HDi;
    const float* kb = g_k + (size_t)bh * Ss * HDi;
    const float* vb = g_v + (size_t)bh * Ss * HDi;

    // Stage Q (pre-scaled by 1/sqrt(HD)=0.125) into QP region, permuted
    #pragma unroll
    for (int p = 0; p < 8; p++) {
        const int idx = tid + p*256;
        const int row = idx >> 4, fc = idx & 15;
        float4 v = *(const float4*)&qb[(size_t)(q0 + row)*HDi + fc*4];
        st_perm(su + QP_OFF, row, fc, v, 0.125f);
    }
    __syncthreads();

    // Q fragments -> registers (rows r0, r0+8 per warp)
    const int r0  = wid*16 + grp;
    const int rx0 = (r0 & 3)*2;
    const int rxg = (grp & 3)*2;
    const int aoff = (2*tig) ^ rx0;
    const int boff = (2*tig) ^ rxg;
    uint32_t qa[8][4];
    #pragma unroll
    for (int g = 0; g < 8; g++) {
        const uint32_t* bp = su + QP_OFF + r0*RS + g*8;
        const uint2 u0 = *(const uint2*)(bp + aoff);
        const uint2 u1 = *(const uint2*)(bp + 8*RS + aoff);
        qa[g][0] = u0.x; qa[g][1] = u1.x; qa[g][2] = u0.y; qa[g][3] = u1.y;
    }

    float o[8][4];
    #pragma unroll
    for (int t = 0; t < 8; t++)
        #pragma unroll
        for (int c = 0; c < 4; c++) o[t][c] = 0.f;
    float m0 = -1e30f, m1 = -1e30f, l0 = 0.f, l1 = 0.f;

    // P store positions for this thread (cols 2tig, 2tig+1 within a group)
    const int p0 = 2*((2*tig) & 3) + ((2*tig) >> 2);
    const int p1 = 2*((2*tig + 1) & 3) + ((2*tig + 1) >> 2);
    const int qg0 = q0 + wid*16 + grp;
    const int qg1 = qg0 + 8;

    const int nkt = 2*qt + 2;
    for (int kt = 0; kt < nkt; kt++) {
        const int k0 = kt * 64;
        __syncthreads();   // Ks/Vts free (prev tile's MMAs done)

        // Load K tile (permuted)
        #pragma unroll
        for (int pp = 0; pp < 4; pp++) {
            const int idx = tid + pp*256;
            const int row = idx >> 4, fc = idx & 15;
            float4 kv = *(const float4*)&kb[(size_t)(k0 + row)*HDi + fc*4];
            st_perm(su + KS_OFF, row, fc, kv, 1.0f);
        }
        // Load V transposed: Vts[d][key] (rotated scatter, conflict-free)
        {
            const int r  = tid >> 2;       // key row 0..63
            const int cl = tid & 3;
            const int kin = r & 7, gk = r >> 3;
            const int pk = 2*(kin & 3) + (kin >> 2);
            #pragma unroll
            for (int t = 0; t < 4; t++) {
                const int dc = cl + 4*t;
                float4 vv = *(const float4*)&vb[(size_t)(k0 + r)*HDi + dc*4];
                const float* f = (const float*)&vv;
                #pragma unroll
                for (int j = 0; j < 4; j++) {
                    const int jj = (j + dc) & 3;
                    const int drow = 4*dc + jj;
                    su[VT_OFF + drow*RS + gk*8 + (pk ^ ((drow & 3)*2))] =
                        f2tf(f[jj]);
                }
            }
        }
        __syncthreads();

        // QK^T -> scores
        float sc[8][4];
        #pragma unroll
        for (int t = 0; t < 8; t++)
            #pragma unroll
            for (int c = 0; c < 4; c++) sc[t][c] = 0.f;
        #pragma unroll
        for (int g = 0; g < 8; g++) {
            #pragma unroll
            for (int nt = 0; nt < 8; nt++) {
                const uint32_t* bp = su + KS_OFF + (nt*8 + grp)*RS + g*8;
                const uint2 bf = *(const uint2*)(bp + boff);
                mma_tf32(sc[nt], qa[g][0], qa[g][1], qa[g][2], qa[g][3],
                         bf.x, bf.y);
            }
        }

        // Causal mask (only near-diagonal tiles)
        if (k0 + 63 > qg0) {
            #pragma unroll
            for (int nt = 0; nt < 8; nt++) {
                const int kg = k0 + nt*8 + 2*tig;
                if (kg     > qg0) sc[nt][0] = -1e30f;
                if (kg + 1 > qg0) sc[nt][1] = -1e30f;
                if (kg     > qg1) sc[nt][2] = -1e30f;
                if (kg + 1 > qg1) sc[nt][3] = -1e30f;
            }
        }

        // Online softmax (rows qg0, qg1), reduce over quad (tig) via shfl
        float mx0 = -1e30f, mx1 = -1e30f;
        #pragma unroll
        for (int nt = 0; nt < 8; nt++) {
            mx0 = fmaxf(mx0, fmaxf(sc[nt][0], sc[nt][1]));
            mx1 = fmaxf(mx1, fmaxf(sc[nt][2], sc[nt][3]));
        }
        mx0 = fmaxf(mx0, __shfl_xor_sync(0xffffffffu, mx0, 1));
        mx0 = fmaxf(mx0, __shfl_xor_sync(0xffffffffu, mx0, 2));
        mx1 = fmaxf(mx1, __shfl_xor_sync(0xffffffffu, mx1, 1));
        mx1 = fmaxf(mx1, __shfl_xor_sync(0xffffffffu, mx1, 2));
        const float mn0 = fmaxf(m0, mx0), mn1 = fmaxf(m1, mx1);
        const float al0 = __expf(m0 - mn0), al1 = __expf(m1 - mn1);
        float s0 = 0.f, s1 = 0.f;
        #pragma unroll
        for (int nt = 0; nt < 8; nt++) {
            sc[nt][0] = __expf(sc[nt][0] - mn0);
            sc[nt][1] = __expf(sc[nt][1] - mn0);
            sc[nt][2] = __expf(sc[nt][2] - mn1);
            sc[nt][3] = __expf(sc[nt][3] - mn1);
            s0 += sc[nt][0] + sc[nt][1];
            s1 += sc[nt][2] + sc[nt][3];
        }
        s0 += __shfl_xor_sync(0xffffffffu, s0, 1);
        s0 += __shfl_xor_sync(0xffffffffu, s0, 2);
        s1 += __shfl_xor_sync(0xffffffffu, s1, 1);
        s1 += __shfl_xor_sync(0xffffffffu, s1, 2);
        l0 = l0*al0 + s0;  m0 = mn0;
        l1 = l1*al1 + s1;  m1 = mn1;
        #pragma unroll
        for (int nt = 0; nt < 8; nt++) {
            o[nt][0] *= al0; o[nt][1] *= al0;
            o[nt][2] *= al1; o[nt][3] *= al1;
        }

        // Store P to this warp's private QP rows (permuted layout)
        #pragma unroll
        for (int nt = 0; nt < 8; nt++) {
            const int base0 = QP_OFF + r0*RS + nt*8;
            su[base0 + (p0 ^ rx0)]        = f2tf(sc[nt][0]);
            su[base0 + (p1 ^ rx0)]        = f2tf(sc[nt][1]);
            su[base0 + 8*RS + (p0 ^ rx0)] = f2tf(sc[nt][2]);
            su[base0 + 8*RS + (p1 ^ rx0)] = f2tf(sc[nt][3]);
        }
        __syncwarp();

        // O += P @ V
        #pragma unroll
        for (int g = 0; g < 8; g++) {
            const uint32_t* ap = su + QP_OFF + r0*RS + g*8;
            const uint2 u0 = *(const uint2*)(ap + aoff);
            const uint2 u1 = *(const uint2*)(ap + 8*RS + aoff);
            #pragma unroll
            for (int nt = 0; nt < 8; nt++) {
                const uint32_t* bp = su + VT_OFF + (nt*8 + grp)*RS + g*8;
                const uint2 bf = *(const uint2*)(bp + boff);
                mma_tf32(o[nt], u0.x, u1.x, u0.y, u1.y, bf.x, bf.y);
            }
        }
        __syncwarp();   // P reads done before next tile's P writes
    }

    // Epilogue: write [B,S,D]
    const float inv0 = 1.f / l0, inv1 = 1.f / l1;
    const int b_ = bh >> 4, h_ = bh & 15;
    float* dst0 = g_ao + ((size_t)(b_*Ss + qg0))*Dd + h_*64;
    float* dst1 = g_ao + ((size_t)(b_*Ss + qg1))*Dd + h_*64;
    #pragma unroll
    for (int nt = 0; nt < 8; nt++) {
        const int col = nt*8 + 2*tig;
        *(float2*)&dst0[col] = make_float2(o[nt][0]*inv0, o[nt][1]*inv0);
        *(float2*)&dst1[col] = make_float2(o[nt][2]*inv1, o[nt][3]*inv1);
    }
}

// ---------------------------------------------------------------------------
extern "C" void kernel_launch(void* const* d_in, const int* in_sizes, int n_in,
                              void* d_out, int out_size)
{
    const float* x  = (const float*)d_in[0];
    const float* fc = (const float*)d_in[1];
    const float* fs = (const float*)d_in[2];
    const float* wq = (const float*)d_in[3];
    const float* wk = (const float*)d_in[4];
    const float* wv = (const float*)d_in[5];
    const float* wo = (const float*)d_in[6];
    float* out = (float*)d_out;

    cudaFuncSetAttribute(gemm_mma<0>, cudaFuncAttributeMaxDynamicSharedMemorySize, GSM);
    cudaFuncSetAttribute(gemm_mma<1>, cudaFuncAttributeMaxDynamicSharedMemorySize, GSM);
    cudaFuncSetAttribute(attn_mma, cudaFuncAttributeMaxDynamicSharedMemorySize, ASMEM);

    // QKV projections (tf32 mma.sync) + RoPE + transpose
    gemm_mma<0><<<dim3(Dd/128, NTOK/128, 3), 256, GSM>>>(x, wq, wk, wv, fc, fs, nullptr);

    // Causal flash attention (tf32 mma.sync)
    attn_mma<<<dim3(Ss/128, Bb*Hh), 256, ASMEM>>>();

    // Output projection (tf32 mma.sync)
    gemm_mma<1><<<dim3(Dd/128, NTOK/128, 1), 256, GSM>>>(nullptr, wo, nullptr, nullptr,
                                                         nullptr, nullptr, out);
}